// round 11
// baseline (speedup 1.0000x reference)
#include <cuda_runtime.h>

// ---------------------------------------------------------------------------
// 256-bin histogram of 33.5M fp32 in [0,255] + count = batchsize*hist[0].
//
// R10: more parallel chains. Stall-bound (46% empty issue slots, all pipes
// ~50%): each warp = one serial acc8 chain; occupancy is the lever.
// TPB 128->96 shrinks the 257-bin u8 column block to 24.7KB -> 9 blocks/SM
// = 27 warps (was 24). Column col(t) = 3*(t&31)+(t>>5): injective over 96,
// warp lanes land on distinct banks within the 24-word bin row.
// Fused addr: bits(fmaf_rz(x,256/255,2^23))*96 + col + 0xE0000000
//            == bin*96 + col (mod 2^32). One FFMA + one IMAD per element.
// R9 ping-pong (2 LDG.128 in flight), FSETP collision correction, fused
// last-block finalize (idempotent for graph replay).
// ---------------------------------------------------------------------------

#define TPB        96
#define SBINS      257                      // 256 bins + spill row (safety)
#define BROW       96                       // bytes per bin row (= TPB columns)
#define WROW       24                       // words per bin row
#define SMEM_WORDS (SBINS * WROW)           // 6168 words = 24672 bytes
#define NBLK       1368                     // 152 SMs * 9 -> exactly one wave

__device__ unsigned int g_hist[256];
__device__ unsigned int g_done;

#define BINC   1.00392156862745f            /* 256/255 */
#define FBIAS  8388608.0f                   /* 2^23 */

// 8 elements of one lane: 8 batched LDS.U8, FSETP collision correction
// (f = 2^23+bin exactly; float equality <=> same bin), 8 ordered STS.U8.
__device__ __forceinline__ void acc8(unsigned char* sh8, unsigned lanoff2,
                                     float4 u, float4 v) {
    float f0 = __fmaf_rz(u.x, BINC, FBIAS), f1 = __fmaf_rz(u.y, BINC, FBIAS);
    float f2 = __fmaf_rz(u.z, BINC, FBIAS), f3 = __fmaf_rz(u.w, BINC, FBIAS);
    float f4 = __fmaf_rz(v.x, BINC, FBIAS), f5 = __fmaf_rz(v.y, BINC, FBIAS);
    float f6 = __fmaf_rz(v.z, BINC, FBIAS), f7 = __fmaf_rz(v.w, BINC, FBIAS);

    unsigned a0 = __float_as_uint(f0) * BROW + lanoff2;
    unsigned a1 = __float_as_uint(f1) * BROW + lanoff2;
    unsigned a2 = __float_as_uint(f2) * BROW + lanoff2;
    unsigned a3 = __float_as_uint(f3) * BROW + lanoff2;
    unsigned a4 = __float_as_uint(f4) * BROW + lanoff2;
    unsigned a5 = __float_as_uint(f5) * BROW + lanoff2;
    unsigned a6 = __float_as_uint(f6) * BROW + lanoff2;
    unsigned a7 = __float_as_uint(f7) * BROW + lanoff2;

    unsigned c0 = sh8[a0], c1 = sh8[a1], c2 = sh8[a2], c3 = sh8[a3];
    unsigned c4 = sh8[a4], c5 = sh8[a5], c6 = sh8[a6], c7 = sh8[a7];

    c0 += 1u;
    c1 += 1u + (f1 == f0);
    c2 += 1u + (f2 == f0) + (f2 == f1);
    c3 += 1u + (f3 == f0) + (f3 == f1) + (f3 == f2);
    c4 += 1u + (f4 == f0) + (f4 == f1) + (f4 == f2) + (f4 == f3);
    c5 += 1u + (f5 == f0) + (f5 == f1) + (f5 == f2) + (f5 == f3) + (f5 == f4);
    c6 += 1u + (f6 == f0) + (f6 == f1) + (f6 == f2) + (f6 == f3) + (f6 == f4)
             + (f6 == f5);
    c7 += 1u + (f7 == f0) + (f7 == f1) + (f7 == f2) + (f7 == f3) + (f7 == f4)
             + (f7 == f5) + (f7 == f6);

    sh8[a0] = (unsigned char)c0; sh8[a1] = (unsigned char)c1;
    sh8[a2] = (unsigned char)c2; sh8[a3] = (unsigned char)c3;
    sh8[a4] = (unsigned char)c4; sh8[a5] = (unsigned char)c5;
    sh8[a6] = (unsigned char)c6; sh8[a7] = (unsigned char)c7;
}

__global__ void __launch_bounds__(TPB, 9)
hist_kernel(const float* __restrict__ inf, const int* __restrict__ bsz,
            float* __restrict__ out, int n) {
    __shared__ unsigned int sh[SMEM_WORDS];
    const int t = threadIdx.x;

    #pragma unroll 4
    for (int i = t; i < SMEM_WORDS; i += TPB) sh[i] = 0u;
    __syncthreads();

    unsigned char* sh8 = (unsigned char*)sh;
    // col injective over [0,96); +0xE0000000 cancels bits(2^23)*96 mod 2^32
    const unsigned lanoff2 = (3u * (t & 31) + (t >> 5)) + 0xE0000000u;

    const int n4 = n >> 2;
    const float4* __restrict__ in4 = (const float4*)inf;
    const int S = gridDim.x * TPB;
    int i = blockIdx.x * TPB + t;

    // ping-pong: one pair (2 LDG.128) in flight while previous pair's
    // 8 elements are accumulated; unrolled x2 to avoid register MOVs.
    float4 p0, p1, q0, q1;
    if (i + S < n4) {
        p0 = in4[i]; p1 = in4[i + S];
        i += 2 * S;
        while (i + S < n4) {
            q0 = in4[i]; q1 = in4[i + S];
            acc8(sh8, lanoff2, p0, p1);
            i += 2 * S;
            if (i + S < n4) {
                p0 = in4[i]; p1 = in4[i + S];
                acc8(sh8, lanoff2, q0, q1);
                i += 2 * S;
            } else {
                acc8(sh8, lanoff2, q0, q1);
                goto remainder;
            }
        }
        acc8(sh8, lanoff2, p0, p1);
    }
remainder:
    for (; i < n4; i += S) {
        float4 x = in4[i];
        float f0 = __fmaf_rz(x.x, BINC, FBIAS), f1 = __fmaf_rz(x.y, BINC, FBIAS);
        float f2 = __fmaf_rz(x.z, BINC, FBIAS), f3 = __fmaf_rz(x.w, BINC, FBIAS);
        unsigned a0 = __float_as_uint(f0) * BROW + lanoff2;
        unsigned a1 = __float_as_uint(f1) * BROW + lanoff2;
        unsigned a2 = __float_as_uint(f2) * BROW + lanoff2;
        unsigned a3 = __float_as_uint(f3) * BROW + lanoff2;
        unsigned c0 = sh8[a0], c1 = sh8[a1], c2 = sh8[a2], c3 = sh8[a3];
        c0 += 1u;
        c1 += 1u + (f1 == f0);
        c2 += 1u + (f2 == f0) + (f2 == f1);
        c3 += 1u + (f3 == f0) + (f3 == f1) + (f3 == f2);
        sh8[a0] = (unsigned char)c0; sh8[a1] = (unsigned char)c1;
        sh8[a2] = (unsigned char)c2; sh8[a3] = (unsigned char)c3;
    }
    if (blockIdx.x == 0 && t < (n & 3)) {      // scalar tail
        unsigned a = __float_as_uint(__fmaf_rz(inf[(n4 << 2) + t], BINC, FBIAS))
                     * BROW + lanoff2;
        sh8[a] = (unsigned char)(sh8[a] + 1);
    }
    __syncthreads();

    // per-bin byte-sum via dp4a; one global atomic per bin per block
    for (int b = t; b < 256; b += TPB) {
        unsigned int s = 0;
        #pragma unroll
        for (int k = 0; k < WROW; k++)
            s = __dp4a(sh[b * WROW + k], 0x01010101u, s);
        atomicAdd(&g_hist[b], s);
    }

    // last arriving block finalizes and resets state (idempotent replays)
    __shared__ unsigned int is_last;
    __shared__ float h0s;
    __threadfence();
    if (t == 0) {
        unsigned ticket = atomicAdd(&g_done, 1u);
        is_last = (ticket == (unsigned)(gridDim.x - 1));
    }
    __syncthreads();
    if (is_last) {
        __threadfence();
        if (t == 0) { h0s = (float)g_hist[0]; g_done = 0u; }
        __syncthreads();
        float c = (float)(*bsz) * h0s;
        for (int b = t; b < 256; b += TPB) {
            out[b]       = (float)g_hist[b];
            out[256 + b] = c;
        }
        __syncthreads();
        for (int b = t; b < 256; b += TPB) g_hist[b] = 0u;
    }
}

extern "C" void kernel_launch(void* const* d_in, const int* in_sizes, int n_in,
                              void* d_out, int out_size) {
    const float* x;
    const int*   bs;
    int n;
    if (n_in >= 2 && in_sizes[0] >= in_sizes[1]) {
        x = (const float*)d_in[0]; bs = (const int*)d_in[1]; n = in_sizes[0];
    } else {
        x = (const float*)d_in[1]; bs = (const int*)d_in[0]; n = in_sizes[1];
    }
    hist_kernel<<<NBLK, TPB>>>(x, bs, (float*)d_out, n);
}

// round 12
// speedup vs baseline: 1.0218x; 1.0218x over previous
#include <cuda_runtime.h>

// ---------------------------------------------------------------------------
// 256-bin histogram of 33.5M fp32 in [0,255] + count = batchsize*hist[0].
//
// R11: acc16 — one 16-deep LDS batch per group (halves per-group LDS-latency
// exposure vs acc8; depth trend: 4->45.7us, 8->36us). Triangular FSETP
// collision correction (120 pairs, fma pipe). 128-byte bank-invariant rows
// (R10 proved 96B rows cause conflicts), u8 per-thread columns, 6 blocks/SM,
// one wave, iteration-deep LDG ping-pong, fused last-block finalize.
// ---------------------------------------------------------------------------

#define TPB        128
#define SBINS      257
#define SMEM_WORDS (SBINS * 32)             // 128B rows -> 32896 bytes
#define NBLK       912                      // 152 SMs * 6 -> one wave

__device__ unsigned int g_hist[256];
__device__ unsigned int g_done;

#define BINC   1.00392156862745f            /* 256/255 */
#define FBIAS  8388608.0f                   /* 2^23 */

// 16 elements of one lane: 16 batched LDS.U8, exact triangular collision
// correction (f = 2^23+bin exactly; float equality <=> same bin; all reads
// precede all writes, last write carries cumulative count), 16 ordered STS.
__device__ __forceinline__ void acc16(unsigned char* sh8, unsigned lanoff2,
                                      float4 p0, float4 p1, float4 p2, float4 p3) {
    float f[16];
    f[0]  = __fmaf_rz(p0.x, BINC, FBIAS); f[1]  = __fmaf_rz(p0.y, BINC, FBIAS);
    f[2]  = __fmaf_rz(p0.z, BINC, FBIAS); f[3]  = __fmaf_rz(p0.w, BINC, FBIAS);
    f[4]  = __fmaf_rz(p1.x, BINC, FBIAS); f[5]  = __fmaf_rz(p1.y, BINC, FBIAS);
    f[6]  = __fmaf_rz(p1.z, BINC, FBIAS); f[7]  = __fmaf_rz(p1.w, BINC, FBIAS);
    f[8]  = __fmaf_rz(p2.x, BINC, FBIAS); f[9]  = __fmaf_rz(p2.y, BINC, FBIAS);
    f[10] = __fmaf_rz(p2.z, BINC, FBIAS); f[11] = __fmaf_rz(p2.w, BINC, FBIAS);
    f[12] = __fmaf_rz(p3.x, BINC, FBIAS); f[13] = __fmaf_rz(p3.y, BINC, FBIAS);
    f[14] = __fmaf_rz(p3.z, BINC, FBIAS); f[15] = __fmaf_rz(p3.w, BINC, FBIAS);

    unsigned a[16], c[16];
    #pragma unroll
    for (int i = 0; i < 16; i++)
        a[i] = __float_as_uint(f[i]) * 128u + lanoff2;  // bin*128 + col (mod 2^32)
    #pragma unroll
    for (int i = 0; i < 16; i++)
        c[i] = sh8[a[i]];                   // 16 LDS in flight
    #pragma unroll
    for (int i = 0; i < 16; i++) {          // overlaps LDS latency
        unsigned inc = 1u;
        #pragma unroll
        for (int j = 0; j < i; j++) inc += (f[i] == f[j]);
        c[i] += inc;
    }
    #pragma unroll
    for (int i = 0; i < 16; i++)
        sh8[a[i]] = (unsigned char)c[i];    // ordered; last write wins
}

__global__ void __launch_bounds__(TPB, 6)
hist_kernel(const float* __restrict__ inf, const int* __restrict__ bsz,
            float* __restrict__ out, int n) {
    __shared__ unsigned int sh[SMEM_WORDS];
    const int t = threadIdx.x;

    #pragma unroll 4
    for (int i = t; i < SMEM_WORDS; i += TPB) sh[i] = 0u;
    __syncthreads();

    unsigned char* sh8 = (unsigned char*)sh;
    // +0x80000000 cancels bits(2^23)*128 mod 2^32 -> addr = bin*128 + col
    const unsigned lanoff2 = (((t & 31) << 2) | (t >> 5)) + 0x80000000u;

    const int n4 = n >> 2;
    const float4* __restrict__ in4 = (const float4*)inf;
    const int S = gridDim.x * TPB;
    int i = blockIdx.x * TPB + t;

    // ping-pong, one full iteration (4x LDG.128) in flight
    float4 p0, p1, p2, p3, q0, q1, q2, q3;
    if (i + 3 * S < n4) {
        p0 = in4[i]; p1 = in4[i + S]; p2 = in4[i + 2 * S]; p3 = in4[i + 3 * S];
        i += 4 * S;
        while (i + 3 * S < n4) {
            q0 = in4[i]; q1 = in4[i + S]; q2 = in4[i + 2 * S]; q3 = in4[i + 3 * S];
            acc16(sh8, lanoff2, p0, p1, p2, p3);
            i += 4 * S;
            if (i + 3 * S < n4) {
                p0 = in4[i]; p1 = in4[i + S]; p2 = in4[i + 2 * S]; p3 = in4[i + 3 * S];
                acc16(sh8, lanoff2, q0, q1, q2, q3);
                i += 4 * S;
            } else {
                acc16(sh8, lanoff2, q0, q1, q2, q3);
                goto remainder;
            }
        }
        acc16(sh8, lanoff2, p0, p1, p2, p3);
    }
remainder:
    for (; i < n4; i += S) {
        float4 x = in4[i];
        float f0 = __fmaf_rz(x.x, BINC, FBIAS), f1 = __fmaf_rz(x.y, BINC, FBIAS);
        float f2 = __fmaf_rz(x.z, BINC, FBIAS), f3 = __fmaf_rz(x.w, BINC, FBIAS);
        unsigned a0 = __float_as_uint(f0) * 128u + lanoff2;
        unsigned a1 = __float_as_uint(f1) * 128u + lanoff2;
        unsigned a2 = __float_as_uint(f2) * 128u + lanoff2;
        unsigned a3 = __float_as_uint(f3) * 128u + lanoff2;
        unsigned c0 = sh8[a0], c1 = sh8[a1], c2 = sh8[a2], c3 = sh8[a3];
        c0 += 1u;
        c1 += 1u + (f1 == f0);
        c2 += 1u + (f2 == f0) + (f2 == f1);
        c3 += 1u + (f3 == f0) + (f3 == f1) + (f3 == f2);
        sh8[a0] = (unsigned char)c0; sh8[a1] = (unsigned char)c1;
        sh8[a2] = (unsigned char)c2; sh8[a3] = (unsigned char)c3;
    }
    if (blockIdx.x == 0 && t < (n & 3)) {      // scalar tail
        unsigned a = __float_as_uint(__fmaf_rz(inf[(n4 << 2) + t], BINC, FBIAS))
                     * 128u + lanoff2;
        sh8[a] = (unsigned char)(sh8[a] + 1);
    }
    __syncthreads();

    // per-bin byte-sum via dp4a; one global atomic per bin per block
    for (int b = t; b < 256; b += TPB) {
        unsigned int s = 0;
        #pragma unroll 8
        for (int k = 0; k < 32; k++)
            s = __dp4a(sh[b * 32 + ((k + t) & 31)], 0x01010101u, s);
        atomicAdd(&g_hist[b], s);
    }

    // last arriving block finalizes and resets state (idempotent replays)
    __shared__ unsigned int is_last;
    __shared__ float h0s;
    __threadfence();
    if (t == 0) {
        unsigned ticket = atomicAdd(&g_done, 1u);
        is_last = (ticket == (unsigned)(gridDim.x - 1));
    }
    __syncthreads();
    if (is_last) {
        __threadfence();
        if (t == 0) { h0s = (float)g_hist[0]; g_done = 0u; }
        __syncthreads();
        float c = (float)(*bsz) * h0s;
        #pragma unroll
        for (int b = t; b < 256; b += TPB) {
            out[b]       = (float)g_hist[b];
            out[256 + b] = c;
        }
        __syncthreads();
        #pragma unroll
        for (int b = t; b < 256; b += TPB) g_hist[b] = 0u;
    }
}

extern "C" void kernel_launch(void* const* d_in, const int* in_sizes, int n_in,
                              void* d_out, int out_size) {
    const float* x;
    const int*   bs;
    int n;
    if (n_in >= 2 && in_sizes[0] >= in_sizes[1]) {
        x = (const float*)d_in[0]; bs = (const int*)d_in[1]; n = in_sizes[0];
    } else {
        x = (const float*)d_in[1]; bs = (const int*)d_in[0]; n = in_sizes[1];
    }
    hist_kernel<<<NBLK, TPB>>>(x, bs, (float*)d_out, n);
}

// round 13
// speedup vs baseline: 1.0272x; 1.0053x over previous
#include <cuda_runtime.h>

// ---------------------------------------------------------------------------
// 256-bin histogram of 33.5M fp32 in [0,255] + count = batchsize*hist[0].
//
// R11: acc16 — one 16-deep LDS batch per group (halves per-group LDS-latency
// exposure vs acc8; depth trend: 4->45.7us, 8->36us). Triangular FSETP
// collision correction (120 pairs, fma pipe). 128-byte bank-invariant rows
// (R10 proved 96B rows cause conflicts), u8 per-thread columns, 6 blocks/SM,
// one wave, iteration-deep LDG ping-pong, fused last-block finalize.
// ---------------------------------------------------------------------------

#define TPB        128
#define SBINS      257
#define SMEM_WORDS (SBINS * 32)             // 128B rows -> 32896 bytes
#define NBLK       912                      // 152 SMs * 6 -> one wave

__device__ unsigned int g_hist[256];
__device__ unsigned int g_done;

#define BINC   1.00392156862745f            /* 256/255 */
#define FBIAS  8388608.0f                   /* 2^23 */

// 16 elements of one lane: 16 batched LDS.U8, exact triangular collision
// correction (f = 2^23+bin exactly; float equality <=> same bin; all reads
// precede all writes, last write carries cumulative count), 16 ordered STS.
__device__ __forceinline__ void acc16(unsigned char* sh8, unsigned lanoff2,
                                      float4 p0, float4 p1, float4 p2, float4 p3) {
    float f[16];
    f[0]  = __fmaf_rz(p0.x, BINC, FBIAS); f[1]  = __fmaf_rz(p0.y, BINC, FBIAS);
    f[2]  = __fmaf_rz(p0.z, BINC, FBIAS); f[3]  = __fmaf_rz(p0.w, BINC, FBIAS);
    f[4]  = __fmaf_rz(p1.x, BINC, FBIAS); f[5]  = __fmaf_rz(p1.y, BINC, FBIAS);
    f[6]  = __fmaf_rz(p1.z, BINC, FBIAS); f[7]  = __fmaf_rz(p1.w, BINC, FBIAS);
    f[8]  = __fmaf_rz(p2.x, BINC, FBIAS); f[9]  = __fmaf_rz(p2.y, BINC, FBIAS);
    f[10] = __fmaf_rz(p2.z, BINC, FBIAS); f[11] = __fmaf_rz(p2.w, BINC, FBIAS);
    f[12] = __fmaf_rz(p3.x, BINC, FBIAS); f[13] = __fmaf_rz(p3.y, BINC, FBIAS);
    f[14] = __fmaf_rz(p3.z, BINC, FBIAS); f[15] = __fmaf_rz(p3.w, BINC, FBIAS);

    unsigned a[16], c[16];
    #pragma unroll
    for (int i = 0; i < 16; i++)
        a[i] = __float_as_uint(f[i]) * 128u + lanoff2;  // bin*128 + col (mod 2^32)
    #pragma unroll
    for (int i = 0; i < 16; i++)
        c[i] = sh8[a[i]];                   // 16 LDS in flight
    #pragma unroll
    for (int i = 0; i < 16; i++) {          // overlaps LDS latency
        unsigned inc = 1u;
        #pragma unroll
        for (int j = 0; j < i; j++) inc += (f[i] == f[j]);
        c[i] += inc;
    }
    #pragma unroll
    for (int i = 0; i < 16; i++)
        sh8[a[i]] = (unsigned char)c[i];    // ordered; last write wins
}

__global__ void __launch_bounds__(TPB, 6)
hist_kernel(const float* __restrict__ inf, const int* __restrict__ bsz,
            float* __restrict__ out, int n) {
    __shared__ unsigned int sh[SMEM_WORDS];
    const int t = threadIdx.x;

    #pragma unroll 4
    for (int i = t; i < SMEM_WORDS; i += TPB) sh[i] = 0u;
    __syncthreads();

    unsigned char* sh8 = (unsigned char*)sh;
    // +0x80000000 cancels bits(2^23)*128 mod 2^32 -> addr = bin*128 + col
    const unsigned lanoff2 = (((t & 31) << 2) | (t >> 5)) + 0x80000000u;

    const int n4 = n >> 2;
    const float4* __restrict__ in4 = (const float4*)inf;
    const int S = gridDim.x * TPB;
    int i = blockIdx.x * TPB + t;

    // ping-pong, one full iteration (4x LDG.128) in flight
    float4 p0, p1, p2, p3, q0, q1, q2, q3;
    if (i + 3 * S < n4) {
        p0 = in4[i]; p1 = in4[i + S]; p2 = in4[i + 2 * S]; p3 = in4[i + 3 * S];
        i += 4 * S;
        while (i + 3 * S < n4) {
            q0 = in4[i]; q1 = in4[i + S]; q2 = in4[i + 2 * S]; q3 = in4[i + 3 * S];
            acc16(sh8, lanoff2, p0, p1, p2, p3);
            i += 4 * S;
            if (i + 3 * S < n4) {
                p0 = in4[i]; p1 = in4[i + S]; p2 = in4[i + 2 * S]; p3 = in4[i + 3 * S];
                acc16(sh8, lanoff2, q0, q1, q2, q3);
                i += 4 * S;
            } else {
                acc16(sh8, lanoff2, q0, q1, q2, q3);
                goto remainder;
            }
        }
        acc16(sh8, lanoff2, p0, p1, p2, p3);
    }
remainder:
    for (; i < n4; i += S) {
        float4 x = in4[i];
        float f0 = __fmaf_rz(x.x, BINC, FBIAS), f1 = __fmaf_rz(x.y, BINC, FBIAS);
        float f2 = __fmaf_rz(x.z, BINC, FBIAS), f3 = __fmaf_rz(x.w, BINC, FBIAS);
        unsigned a0 = __float_as_uint(f0) * 128u + lanoff2;
        unsigned a1 = __float_as_uint(f1) * 128u + lanoff2;
        unsigned a2 = __float_as_uint(f2) * 128u + lanoff2;
        unsigned a3 = __float_as_uint(f3) * 128u + lanoff2;
        unsigned c0 = sh8[a0], c1 = sh8[a1], c2 = sh8[a2], c3 = sh8[a3];
        c0 += 1u;
        c1 += 1u + (f1 == f0);
        c2 += 1u + (f2 == f0) + (f2 == f1);
        c3 += 1u + (f3 == f0) + (f3 == f1) + (f3 == f2);
        sh8[a0] = (unsigned char)c0; sh8[a1] = (unsigned char)c1;
        sh8[a2] = (unsigned char)c2; sh8[a3] = (unsigned char)c3;
    }
    if (blockIdx.x == 0 && t < (n & 3)) {      // scalar tail
        unsigned a = __float_as_uint(__fmaf_rz(inf[(n4 << 2) + t], BINC, FBIAS))
                     * 128u + lanoff2;
        sh8[a] = (unsigned char)(sh8[a] + 1);
    }
    __syncthreads();

    // per-bin byte-sum via dp4a; one global atomic per bin per block
    for (int b = t; b < 256; b += TPB) {
        unsigned int s = 0;
        #pragma unroll 8
        for (int k = 0; k < 32; k++)
            s = __dp4a(sh[b * 32 + ((k + t) & 31)], 0x01010101u, s);
        atomicAdd(&g_hist[b], s);
    }

    // last arriving block finalizes and resets state (idempotent replays)
    __shared__ unsigned int is_last;
    __shared__ float h0s;
    __threadfence();
    if (t == 0) {
        unsigned ticket = atomicAdd(&g_done, 1u);
        is_last = (ticket == (unsigned)(gridDim.x - 1));
    }
    __syncthreads();
    if (is_last) {
        __threadfence();
        if (t == 0) { h0s = (float)g_hist[0]; g_done = 0u; }
        __syncthreads();
        float c = (float)(*bsz) * h0s;
        #pragma unroll
        for (int b = t; b < 256; b += TPB) {
            out[b]       = (float)g_hist[b];
            out[256 + b] = c;
        }
        __syncthreads();
        #pragma unroll
        for (int b = t; b < 256; b += TPB) g_hist[b] = 0u;
    }
}

extern "C" void kernel_launch(void* const* d_in, const int* in_sizes, int n_in,
                              void* d_out, int out_size) {
    const float* x;
    const int*   bs;
    int n;
    if (n_in >= 2 && in_sizes[0] >= in_sizes[1]) {
        x = (const float*)d_in[0]; bs = (const int*)d_in[1]; n = in_sizes[0];
    } else {
        x = (const float*)d_in[1]; bs = (const int*)d_in[0]; n = in_sizes[1];
    }
    hist_kernel<<<NBLK, TPB>>>(x, bs, (float*)d_out, n);
}